// round 8
// baseline (speedup 1.0000x reference)
#include <cuda_runtime.h>
#include <cuda_bf16.h>

// RelativeAttention: B=2,H=8,S=512,D=64
// scores=(Q.K+Q.R[q,k])/8, mask(-1e9), softmax, mask(0), out=p@V
// ~50% of R's 1.07GB skipped via mask compaction. Single fused pass:
//   - R: 4-stage cp.async ring (CHUNK=4 rows), prefetch distance 3 -> DRAM
//     latency amortized across chunks (round-7 lesson: depth, not luck).
//   - K: register double-buffer prefetched 2 chunks ahead (L2-hot).
//   - mask bits eliminated: p_sh init to -8e9; exp underflow gives exact 0.
// Outputs concatenated in d_out: out [B,H,S,D] then p_attn [B,H,S,S].

#define Bc 2
#define Hc 8
#define Sc 512
#define Dc 64
#define TQ 4          // query rows per tile (one per warp)
#define THREADS 128
#define NTILES 2048
#define GRIDSZ 1024   // 2 contiguous tiles per CTA; 7 CTAs/SM -> all resident
#define CHUNK 4       // R rows per pipeline stage per warp
#define STAGES 4
#define FULLM 0xffffffffu

__device__ __forceinline__ unsigned su32(const void* p) {
    return (unsigned)__cvta_generic_to_shared(p);
}
__device__ __forceinline__ void cp_async16(unsigned sa, const void* g) {
    asm volatile("cp.async.cg.shared.global [%0], [%1], 16;" :: "r"(sa), "l"(g));
}
__device__ __forceinline__ void cp_commit() {
    asm volatile("cp.async.commit_group;" ::: "memory");
}
template<int N> __device__ __forceinline__ void cp_wait() {
    asm volatile("cp.async.wait_group %0;" :: "n"(N) : "memory");
}

__global__ __launch_bounds__(THREADS, 7)   // 72-reg budget, 7 CTAs/SM
void relattn_kernel(const float* __restrict__ Q, const float* __restrict__ K,
                    const float* __restrict__ V, const float* __restrict__ R,
                    const int* __restrict__ M,
                    float* __restrict__ out, float* __restrict__ p_out)
{
    __shared__ float q_sh[TQ][Dc];                     // 1 KB
    __shared__ float p_sh[TQ][Sc];                     // 8 KB
    __shared__ unsigned short idx_sh[TQ][Sc + 16];     // 4.1 KB
    __shared__ float r_buf[TQ][STAGES][CHUNK][Dc];     // 16 KB (R ring)

    const int tid  = threadIdx.x;
    const int w    = tid >> 5;
    const int lane = tid & 31;
    const int rg   = lane >> 3;          // row within chunk (4 rows)
    const int l8   = lane & 7;           // float4 slot in half-row
    const int prow = lane >> 4;          // fill: row pair selector
    const int pcol = (lane & 15) << 2;   // fill: float offset (16B granule)

    for (int ti = 0; ti < 2; ++ti) {
        const int t  = blockIdx.x * 2 + ti;      // contiguous -> (b,h) L1 reuse
        const int qt = t & (Sc / TQ - 1);
        const int h  = (t >> 7) & (Hc - 1);
        const int b  = t >> 10;

        const int q0 = qt * TQ;
        const int qrow = q0 + w;
        const long bh = (long)b * Hc + h;

        const float* Qb   = Q + (bh * Sc + q0) * Dc;
        const float* Kb   = K + bh * Sc * Dc;
        const float* Vb   = V + bh * Sc * Dc;
        const float* Rrow = R + ((bh * Sc + (long)qrow) * (long)Sc) * Dc;
        const int*   Mrow = M + (((long)b * Sc + qrow) * Sc);

        __syncthreads();                 // q_sh/r_buf reuse across tiles
        for (int i = tid; i < TQ * Dc; i += THREADS)
            q_sh[i / Dc][i % Dc] = Qb[i];
        __syncthreads();

        // ---- per-warp mask compaction into dense index list ----
        int cnt = 0;
        #pragma unroll
        for (int i = 0; i < Sc / 32; ++i) {
            const int kk = i * 32 + lane;
            const bool m = (__ldg(Mrow + kk) != 0);
            const unsigned bal = __ballot_sync(FULLM, m);
            const int pos = cnt + __popc(bal & ((1u << lane) - 1u));
            if (m) idx_sh[w][pos] = (unsigned short)kk;
            cnt += __popc(bal);
        }
        __syncwarp();
        if (lane < 16) idx_sh[w][cnt + lane] = (cnt > 0) ? idx_sh[w][0] : (unsigned short)0;

        // ---- init scores to "masked": -8e9 * 0.125 = -1e9 ----
        #pragma unroll
        for (int i = 0; i < Sc / 32; ++i) p_sh[w][lane + 32 * i] = -8.0e9f;
        __syncwarp();

        const float4 qa = ((const float4*)q_sh[w])[l8];
        const float4 qb = ((const float4*)q_sh[w])[l8 + 8];
        const int nch = (cnt + CHUNK - 1) / CHUNK;

        // R fill: chunk j -> stage j&3 (1KB, 2 cp.async per lane)
        auto fillR = [&](int j) {
            const int nb = j * CHUNK;
            const int s = j & (STAGES - 1);
            #pragma unroll
            for (int r = 0; r < 2; ++r) {
                const int rowin = r * 2 + prow;
                const int kk = (int)idx_sh[w][nb + rowin];       // pad-safe
                cp_async16(su32(&r_buf[w][s][rowin][pcol]),
                           Rrow + (long)kk * Dc + pcol);
            }
        };

        // K register ring, prefetch distance 2
        float4 kA[2], kB[2];
        auto loadK = [&](int j, int slot) {
            const int kk = (int)idx_sh[w][j * CHUNK + rg];        // pad-safe
            const float* krow = Kb + (long)kk * Dc;
            kA[slot] = __ldg((const float4*)krow + l8);
            kB[slot] = __ldg((const float4*)krow + l8 + 8);
        };

        // prologue: 3 chunks of R committed, 2 chunks of K in regs
        #pragma unroll
        for (int j = 0; j < STAGES - 1; ++j) {
            if (j < nch) fillR(j);
            cp_commit();
        }
        loadK(0, 0);
        loadK(1, 1);

        // ---- fused consume loop: zero exposed load latency ----
        for (int c = 0; c < nch; ++c) {
            if (c + 3 < nch) fillR(c + 3);
            cp_commit();
            cp_wait<STAGES - 1>();       // chunk c landed
            __syncwarp();

            const int s = c & (STAGES - 1);
            const int jj = c * CHUNK + rg;
            const int kk = (int)idx_sh[w][jj];
            const float4 ka = kA[c & 1];
            const float4 kb = kB[c & 1];
            const float4 ra = *(const float4*)&r_buf[w][s][rg][l8 << 2];
            const float4 rb = *(const float4*)&r_buf[w][s][rg][(l8 << 2) + 32];
            float sd = qa.x * (ra.x + ka.x) + qa.y * (ra.y + ka.y)
                     + qa.z * (ra.z + ka.z) + qa.w * (ra.w + ka.w)
                     + qb.x * (rb.x + kb.x) + qb.y * (rb.y + kb.y)
                     + qb.z * (rb.z + kb.z) + qb.w * (rb.w + kb.w);
            sd += __shfl_xor_sync(FULLM, sd, 4);
            sd += __shfl_xor_sync(FULLM, sd, 2);
            sd += __shfl_xor_sync(FULLM, sd, 1);
            if (l8 == 0 && jj < cnt) p_sh[w][kk] = sd;

            if (c + 2 < nch) loadK(c + 2, c & 1);

            __syncwarp();                // stage s fully read before refill at c+1
        }

        // ---- softmax: masked entries underflow to exact 0 ----
        float vals[Sc / 32];
        float mx = -3.0e38f;
        #pragma unroll
        for (int i = 0; i < Sc / 32; ++i) {
            const float sv = p_sh[w][lane + 32 * i] * 0.125f;     // masked -> -1e9
            vals[i] = sv;
            mx = fmaxf(mx, sv);
        }
        #pragma unroll
        for (int o = 16; o; o >>= 1) mx = fmaxf(mx, __shfl_xor_sync(FULLM, mx, o));
        float sum = 0.f;
        #pragma unroll
        for (int i = 0; i < Sc / 32; ++i) {
            const float e = __expf(vals[i] - mx);                 // masked -> 0.0f
            vals[i] = e;
            sum += e;
        }
        #pragma unroll
        for (int o = 16; o; o >>= 1) sum += __shfl_xor_sync(FULLM, sum, o);
        const float inv = 1.0f / sum;

        float* prow2 = p_out + (bh * Sc + (long)qrow) * Sc;
        #pragma unroll
        for (int i = 0; i < Sc / 32; ++i) {
            const int kk = lane + 32 * i;
            const float p = vals[i] * inv;                        // exact 0 if masked
            p_sh[w][kk] = p;
            __stcs(prow2 + kk, p);
        }
        __syncwarp();

        // ---- AV over compacted indices ----
        float2 acc0 = make_float2(0.f, 0.f), acc1 = make_float2(0.f, 0.f);
        const int cnt2 = (cnt + 1) & ~1;
        #pragma unroll 4
        for (int j = 0; j < cnt2; j += 2) {
            const int k0 = (int)idx_sh[w][j];
            const int k1 = (int)idx_sh[w][j + 1];
            const float p0 = p_sh[w][k0];
            const float p1 = (j + 1 < cnt) ? p_sh[w][k1] : 0.f;
            const float2 v0 = __ldg((const float2*)(Vb + (long)k0 * Dc) + lane);
            const float2 v1 = __ldg((const float2*)(Vb + (long)k1 * Dc) + lane);
            acc0.x += p0 * v0.x; acc0.y += p0 * v0.y;
            acc1.x += p1 * v1.x; acc1.y += p1 * v1.y;
        }
        float* orow = out + (bh * Sc + (long)qrow) * Dc;
        ((float2*)orow)[lane] = make_float2(acc0.x + acc1.x, acc0.y + acc1.y);
    }
}

extern "C" void kernel_launch(void* const* d_in, const int* in_sizes, int n_in,
                              void* d_out, int out_size)
{
    const float* Q = (const float*)d_in[0];
    const float* K = (const float*)d_in[1];
    const float* V = (const float*)d_in[2];
    const float* R = (const float*)d_in[3];
    const int*   M = (const int*)d_in[4];

    float* out   = (float*)d_out;                    // [B,H,S,D]
    float* p_out = out + (long)Bc * Hc * Sc * Dc;    // [B,H,S,S] appended

    relattn_kernel<<<GRIDSZ, THREADS>>>(Q, K, V, R, M, out, p_out);
}

// round 11
// speedup vs baseline: 1.4283x; 1.4283x over previous
#include <cuda_runtime.h>
#include <cuda_bf16.h>

// RelativeAttention: B=2,H=8,S=512,D=64
// scores=(Q.K+Q.R[q,k])/8, mask(-1e9), softmax, mask(0), out=p@V
// ~50% of R's 1.07GB skipped via mask compaction. Round-6 pipeline shape
// (2-stage CHUNK=8 cp.async ring, K fused in consume) + ZERO block barriers:
// every warp is fully autonomous, so softmax/AV (DRAM-idle) of one warp
// overlaps R-streaming of others -> higher DRAM duty cycle (round-8 lesson:
// the convoy, not MLP, was the limiter).
// Outputs concatenated in d_out: out [B,H,S,D] then p_attn [B,H,S,S].

#define Bc 2
#define Hc 8
#define Sc 512
#define Dc 64
#define TQ 4          // query rows per tile (one per warp)
#define THREADS 128
#define GRIDSZ 1024   // 2 contiguous tiles per CTA; 7 CTAs/SM -> all resident
#define CHUNK 8
#define FULLM 0xffffffffu

__device__ __forceinline__ unsigned su32(const void* p) {
    return (unsigned)__cvta_generic_to_shared(p);
}
__device__ __forceinline__ void cp_async16(unsigned sa, const void* g) {
    asm volatile("cp.async.cg.shared.global [%0], [%1], 16;" :: "r"(sa), "l"(g));
}
__device__ __forceinline__ void cp_commit() {
    asm volatile("cp.async.commit_group;" ::: "memory");
}
template<int N> __device__ __forceinline__ void cp_wait() {
    asm volatile("cp.async.wait_group %0;" :: "n"(N) : "memory");
}

__global__ __launch_bounds__(THREADS, 7)   // 72-reg budget, 7 CTAs/SM
void relattn_kernel(const float* __restrict__ Q, const float* __restrict__ K,
                    const float* __restrict__ V, const float* __restrict__ R,
                    const int* __restrict__ M,
                    float* __restrict__ out, float* __restrict__ p_out)
{
    __shared__ float p_sh[TQ][Sc];                     // 8 KB   (per-warp slice)
    __shared__ unsigned short idx_sh[TQ][Sc + 16];     // 4.1 KB (per-warp slice)
    __shared__ float r_buf[TQ][2][CHUNK][Dc];          // 16 KB  (per-warp slice)

    const int tid  = threadIdx.x;
    const int w    = tid >> 5;
    const int lane = tid & 31;
    const int rg   = lane >> 3;          // row-in-group (4 rows per half)
    const int l8   = lane & 7;           // float4 slot in half-row
    const int prow = lane >> 4;          // fill: row pair selector
    const int pcol = (lane & 15) << 2;   // fill: float offset (16B granule)

    for (int ti = 0; ti < 2; ++ti) {
        const int t  = blockIdx.x * 2 + ti;      // contiguous -> (b,h) L2 reuse
        const int qt = t & (Sc / TQ - 1);
        const int h  = (t >> 7) & (Hc - 1);
        const int b  = t >> 10;

        const int qrow = qt * TQ + w;
        const long bh = (long)b * Hc + h;

        const float* Kb   = K + bh * Sc * Dc;
        const float* Vb   = V + bh * Sc * Dc;
        const float* Qrow = Q + (bh * Sc + (long)qrow) * Dc;
        const float* Rrow = R + ((bh * Sc + (long)qrow) * (long)Sc) * Dc;
        const int*   Mrow = M + (((long)b * Sc + qrow) * Sc);

        // q directly into registers (no smem, no block barrier)
        const float4 qa = __ldg((const float4*)Qrow + l8);
        const float4 qb = __ldg((const float4*)Qrow + l8 + 8);

        // ---- per-warp mask compaction into dense index list ----
        int cnt = 0;
        #pragma unroll
        for (int i = 0; i < Sc / 32; ++i) {
            const int kk = i * 32 + lane;
            const bool m = (__ldg(Mrow + kk) != 0);
            const unsigned bal = __ballot_sync(FULLM, m);
            const int pos = cnt + __popc(bal & ((1u << lane) - 1u));
            if (m) idx_sh[w][pos] = (unsigned short)kk;
            cnt += __popc(bal);
        }
        __syncwarp();
        if (lane < 16) idx_sh[w][cnt + lane] = (cnt > 0) ? idx_sh[w][0] : (unsigned short)0;

        // ---- init scores "masked": -8e9 * 0.125 = -1e9 -> exp underflow -> 0
        #pragma unroll
        for (int i = 0; i < 4; ++i)
            ((float4*)p_sh[w])[lane + 32 * i] = make_float4(-8e9f, -8e9f, -8e9f, -8e9f);
        __syncwarp();

        const int nch = (cnt + CHUNK - 1) / CHUNK;

        auto fillR = [&](int j) {                      // chunk j -> stage j&1
            const int nb = j * CHUNK;
            const int s = j & 1;
            #pragma unroll
            for (int r = 0; r < 4; ++r) {
                const int rowin = r * 2 + prow;
                const int kk = (int)idx_sh[w][nb + rowin];       // pad-safe
                cp_async16(su32(&r_buf[w][s][rowin][pcol]),
                           Rrow + (long)kk * Dc + pcol);
            }
        };

        if (nch > 0) { fillR(0); cp_commit(); }

        for (int c = 0; c < nch; ++c) {
            const int s = c & 1;
            const int base = c * CHUNK;
            if (c + 1 < nch) { fillR(c + 1); cp_commit(); cp_wait<1>(); }
            else             { cp_wait<0>(); }
            __syncwarp();

            // batch ALL loads for both halves, then compute
            const int jj0 = base + rg, jj1 = base + 4 + rg;
            const int kk0 = (int)idx_sh[w][jj0];
            const int kk1 = (int)idx_sh[w][jj1];
            const float* kr0 = Kb + (long)kk0 * Dc;
            const float* kr1 = Kb + (long)kk1 * Dc;
            const float4 ka0 = __ldg((const float4*)kr0 + l8);
            const float4 kb0 = __ldg((const float4*)kr0 + l8 + 8);
            const float4 ka1 = __ldg((const float4*)kr1 + l8);
            const float4 kb1 = __ldg((const float4*)kr1 + l8 + 8);
            const float4 ra0 = *(const float4*)&r_buf[w][s][rg][l8 << 2];
            const float4 rb0 = *(const float4*)&r_buf[w][s][rg][(l8 << 2) + 32];
            const float4 ra1 = *(const float4*)&r_buf[w][s][4 + rg][l8 << 2];
            const float4 rb1 = *(const float4*)&r_buf[w][s][4 + rg][(l8 << 2) + 32];

            float s0 = qa.x * (ra0.x + ka0.x) + qa.y * (ra0.y + ka0.y)
                     + qa.z * (ra0.z + ka0.z) + qa.w * (ra0.w + ka0.w)
                     + qb.x * (rb0.x + kb0.x) + qb.y * (rb0.y + kb0.y)
                     + qb.z * (rb0.z + kb0.z) + qb.w * (rb0.w + kb0.w);
            float s1 = qa.x * (ra1.x + ka1.x) + qa.y * (ra1.y + ka1.y)
                     + qa.z * (ra1.z + ka1.z) + qa.w * (ra1.w + ka1.w)
                     + qb.x * (rb1.x + kb1.x) + qb.y * (rb1.y + kb1.y)
                     + qb.z * (rb1.z + kb1.z) + qb.w * (rb1.w + kb1.w);
            s0 += __shfl_xor_sync(FULLM, s0, 4);
            s0 += __shfl_xor_sync(FULLM, s0, 2);
            s0 += __shfl_xor_sync(FULLM, s0, 1);
            s1 += __shfl_xor_sync(FULLM, s1, 4);
            s1 += __shfl_xor_sync(FULLM, s1, 2);
            s1 += __shfl_xor_sync(FULLM, s1, 1);
            if (l8 == 0 && jj0 < cnt) p_sh[w][kk0] = s0;
            if (l8 == 0 && jj1 < cnt) p_sh[w][kk1] = s1;

            __syncwarp();                // stage s fully read before refill
        }

        // ---- softmax: masked entries underflow to exact 0 ----
        float vals[Sc / 32];
        float mx = -3.0e38f;
        #pragma unroll
        for (int i = 0; i < Sc / 32; ++i) {
            const float sv = p_sh[w][lane + 32 * i] * 0.125f;
            vals[i] = sv;
            mx = fmaxf(mx, sv);
        }
        #pragma unroll
        for (int o = 16; o; o >>= 1) mx = fmaxf(mx, __shfl_xor_sync(FULLM, mx, o));
        float sum = 0.f;
        #pragma unroll
        for (int i = 0; i < Sc / 32; ++i) {
            const float e = __expf(vals[i] - mx);
            vals[i] = e;
            sum += e;
        }
        #pragma unroll
        for (int o = 16; o; o >>= 1) sum += __shfl_xor_sync(FULLM, sum, o);
        const float inv = 1.0f / sum;

        float* prow2 = p_out + (bh * Sc + (long)qrow) * Sc;
        #pragma unroll
        for (int i = 0; i < Sc / 32; ++i) {
            const int kk = lane + 32 * i;
            const float p = vals[i] * inv;            // exact 0 if masked
            p_sh[w][kk] = p;
            __stcs(prow2 + kk, p);
        }
        __syncwarp();

        // ---- AV over compacted indices: 4 rows/iter for V-load MLP ----
        float2 acc0 = make_float2(0.f, 0.f), acc1 = make_float2(0.f, 0.f);
        const int cnt4 = (cnt + 3) & ~3;
        #pragma unroll 2
        for (int j = 0; j < cnt4; j += 4) {
            const int k0 = (int)idx_sh[w][j];
            const int k1 = (int)idx_sh[w][j + 1];
            const int k2 = (int)idx_sh[w][j + 2];
            const int k3 = (int)idx_sh[w][j + 3];
            const float2 v0 = __ldg((const float2*)(Vb + (long)k0 * Dc) + lane);
            const float2 v1 = __ldg((const float2*)(Vb + (long)k1 * Dc) + lane);
            const float2 v2 = __ldg((const float2*)(Vb + (long)k2 * Dc) + lane);
            const float2 v3 = __ldg((const float2*)(Vb + (long)k3 * Dc) + lane);
            const float p0 = p_sh[w][k0];
            const float p1 = (j + 1 < cnt) ? p_sh[w][k1] : 0.f;
            const float p2 = (j + 2 < cnt) ? p_sh[w][k2] : 0.f;
            const float p3 = (j + 3 < cnt) ? p_sh[w][k3] : 0.f;
            acc0.x += p0 * v0.x; acc0.y += p0 * v0.y;
            acc1.x += p1 * v1.x; acc1.y += p1 * v1.y;
            acc0.x += p2 * v2.x; acc0.y += p2 * v2.y;
            acc1.x += p3 * v3.x; acc1.y += p3 * v3.y;
        }
        float* orow = out + (bh * Sc + (long)qrow) * Dc;
        ((float2*)orow)[lane] = make_float2(acc0.x + acc1.x, acc0.y + acc1.y);
    }
}

extern "C" void kernel_launch(void* const* d_in, const int* in_sizes, int n_in,
                              void* d_out, int out_size)
{
    const float* Q = (const float*)d_in[0];
    const float* K = (const float*)d_in[1];
    const float* V = (const float*)d_in[2];
    const float* R = (const float*)d_in[3];
    const int*   M = (const int*)d_in[4];

    float* out   = (float*)d_out;                    // [B,H,S,D]
    float* p_out = out + (long)Bc * Hc * Sc * Dc;    // [B,H,S,S] appended

    relattn_kernel<<<GRIDSZ, THREADS>>>(Q, K, V, R, M, out, p_out);
}